// round 10
// baseline (speedup 1.0000x reference)
#include <cuda_runtime.h>
#include <cuda_bf16.h>
#include <cstdint>

// Problem constants
#define B_ 2
#define H_ 8
#define N_ 512
#define D_ 16
#define E_ 128
#define HD 128
#define TM 64
#define THREADS 512
#define NJOBS_TOTAL (B_ * N_)          // 1024

// smem layout (bytes). A/W rows are 128 bf16 = 256 B. All tiles 1024-aligned.
#define SM_Q     0                      // 2 x 512  q (parity)
#define SM_RED   1024                   // 64       tail softmax partials
#define SM_OBUF  1088                   // 512      tail output partials
#define SM_S     2048                   // 2 x 16384 scores (parity)
#define SM_A     34816                  // 2 x 32768 {z_hi, z_lo} double buffer
#define SM_ABUF  32768
#define SM_ALO   16384
#define SM_WH    100352                 // 65536  W_hi [256n][128k] (d-permuted, interleaved)
#define SM_WL    165888                 // 65536  W_lo
#define SM_TOTAL 231424

__device__ __forceinline__ uint32_t smem_u32(const void* p) {
    uint32_t r;
    asm("{ .reg .u64 t; cvta.to.shared.u64 t, %1; cvt.u32.u64 %0, t; }" : "=r"(r) : "l"(p));
    return r;
}
__device__ __forceinline__ void ldsm_x4(uint32_t (&r)[4], uint32_t addr) {
    asm volatile("ldmatrix.sync.aligned.m8n8.x4.shared.b16 {%0,%1,%2,%3}, [%4];"
                 : "=r"(r[0]), "=r"(r[1]), "=r"(r[2]), "=r"(r[3]) : "r"(addr));
}
#define MMA_BF16(d, a, b0v, b1v) \
    asm volatile("mma.sync.aligned.m16n8k16.row.col.f32.bf16.bf16.f32 " \
        "{%0,%1,%2,%3}, {%4,%5,%6,%7}, {%8,%9}, {%0,%1,%2,%3};" \
        : "+f"((d)[0]), "+f"((d)[1]), "+f"((d)[2]), "+f"((d)[3]) \
        : "r"((a)[0]), "r"((a)[1]), "r"((a)[2]), "r"((a)[3]), "r"(b0v), "r"(b1v))

__device__ __forceinline__ uint32_t pack_bf2(float a, float b) {
    __nv_bfloat162 p = __float22bfloat162_rn(make_float2(a, b));  // .x=a (low half)
    return *reinterpret_cast<uint32_t*>(&p);
}
__device__ __forceinline__ float bf_lo(uint32_t w) { return __uint_as_float(w << 16); }
__device__ __forceinline__ float bf_hi(uint32_t w) { return __uint_as_float(w & 0xFFFF0000u); }

// z row pointer for global tile s of this CTA's job stream
__device__ __forceinline__ const float* zptr(const float* z, int cta, int stride,
                                             int s, int mrow, int e0) {
    int jb = cta + (s >> 3) * stride;
    int b = jb >> 9, n = jb & 511;
    return z + ((((size_t)b * N_ + n) * N_) + (s & 7) * TM + mrow) * E_ + e0;
}

__global__ void __launch_bounds__(THREADS, 1)
mixed_attn_persist(const float* __restrict__ q, const float* __restrict__ k,
                   const float* __restrict__ v, const float* __restrict__ z,
                   const float* __restrict__ Wz1, const float* __restrict__ Wz2,
                   float* __restrict__ out)
{
    extern __shared__ char smem[];
    const uint32_t smem_base = smem_u32(smem);
    float* red_sm = (float*)(smem + SM_RED);
    float* obuf   = (float*)(smem + SM_OBUF);

    const int tid  = threadIdx.x;
    const int wid  = tid >> 5;
    const int lane = tid & 31;
    const int g    = lane >> 2;
    const int tig  = lane & 3;
    const int cta    = blockIdx.x;
    const int stride = gridDim.x;
    const int njobs  = (NJOBS_TOTAL - cta + stride - 1) / stride;
    const int nwin   = njobs * 8;

    // convert-warp mapping (wid 8..11): 16 rows per warp, 2 e-halves
    const int mrow = ((wid - 8) & 3) * 16 + (lane >> 1);
    const int e0c  = (lane & 1) * 64;
    float4 zreg[16];

    // ======================= PROLOGUE =======================
    if (wid < 8) {
        // q for job 0 -> parity buffer 0
        if (tid < HD) {
            int b0 = cta >> 9, n0 = cta & 511;
            int h = tid >> 4, d = tid & 15;
            ((float*)(smem + SM_Q))[tid] = q[(((size_t)b0 * H_ + h) * N_ + n0) * D_ + d];
        }
        // W -> bf16 hi/lo, d-PERMUTED columns (fragment (ntl,tig) sees d = 4*tig+ntl):
        //   nn: h = nn>>5, ntl = (nn>>3)&3, tg = (nn>>1)&3, src = nn&1
        //   source col c = h*16 + 4*tg + ntl of (src? Wz2 : Wz1)
        const int nn = tid;
        const float* Wsrc = (nn & 1) ? Wz2 : Wz1;
        const int c = (nn >> 5) * 16 + ((nn >> 1) & 3) * 4 + ((nn >> 3) & 3);
        char* WHp = smem + SM_WH + nn * 256;
        char* WLp = smem + SM_WL + nn * 256;
        const int xr = (nn & 7);
        #pragma unroll 4
        for (int e = 0; e < E_; e += 2) {
            float w0 = Wsrc[e * HD + c];
            float w1 = Wsrc[(e + 1) * HD + c];
            uint32_t hi = pack_bf2(w0, w1);
            uint32_t lo = pack_bf2(w0 - bf_lo(hi), w1 - bf_hi(hi));
            int sw = ((((e >> 3) ^ xr) << 4)) + (e & 7) * 2;
            *(uint32_t*)(WHp + sw) = hi;
            *(uint32_t*)(WLp + sw) = lo;
        }
    } else if (wid < 12) {
        // convert warps: tile 0 -> A0, then prefetch tile 1
        const float4* zp0 = (const float4*)zptr(z, cta, stride, 0, mrow, e0c);
        #pragma unroll
        for (int j = 0; j < 16; j++) zreg[j] = zp0[j];
        {
            char* AH = smem + SM_A + mrow * 256;
            char* AL = AH + SM_ALO;
            const int xr = mrow & 7;
            #pragma unroll
            for (int j = 0; j < 16; j++) {
                const int e = e0c + j * 4;
                float4 f = zreg[j];
                uint32_t h01 = pack_bf2(f.x, f.y);
                uint32_t h23 = pack_bf2(f.z, f.w);
                uint32_t l01 = pack_bf2(f.x - bf_lo(h01), f.y - bf_hi(h01));
                uint32_t l23 = pack_bf2(f.z - bf_lo(h23), f.w - bf_hi(h23));
                int sw = (((e >> 3) ^ xr) << 4) + (e & 4) * 2;
                *(uint2*)(AH + sw) = make_uint2(h01, h23);
                *(uint2*)(AL + sw) = make_uint2(l01, l23);
            }
        }
        if (nwin > 1) {
            const float4* zp1 = (const float4*)zptr(z, cta, stride, 1, mrow, e0c);
            #pragma unroll
            for (int j = 0; j < 16; j++) zreg[j] = zp1[j];
        }
    }
    __syncthreads();

    // consumer tiling (wid 0..7): 2 m-blocks (32 rows) x 4 n-blocks (64 cols = 2 heads)
    const int mblk  = (wid & 1) * 32;
    const int nq    = wid >> 1;
    const int nbase = nq * 64;
    const int laneX = lane & 7;
    const uint32_t arow_off = (uint32_t)(mblk + ((lane >> 3) & 1) * 8 + laneX) * 256;
    const int asel = lane >> 4;
    const uint32_t brow = smem_base + (uint32_t)(nbase + ((lane >> 4) & 1) * 8 + laneX) * 256;
    const int bsel = (lane >> 3) & 1;
    const int w2 = wid - 12;               // softmax warp index 0..3

    // ======================= JOB LOOP =======================
    int idx = 0;
    for (int job = cta; job < NJOBS_TOTAL; job += stride, idx++) {
        const int parity = idx & 1;
        const int b = job >> 9;
        const int pj = job - stride;       // previous job (softmax target), <0 if none
        float* s_cur = (float*)(smem + SM_S) + parity * (H_ * N_);
        float* s_prev = (float*)(smem + SM_S) + (parity ^ 1) * (H_ * N_);
        const float* q_cur = (float*)(smem + SM_Q) + parity * HD;

        // softmax state (persists across the 8 windows; used by wid 12..15)
        float sm_sum0 = 0.f, sm_sum1 = 0.f, sm_oacc = 0.f;

        for (int t = 0; t < 8; t++) {
            if (wid < 8) {
                // ---------------- MMA + score epilogue ----------------
                const uint32_t abase = smem_base + SM_A + (uint32_t)(t & 1) * SM_ABUF + arow_off;
                float acc[2][8][4];
                #pragma unroll
                for (int mt = 0; mt < 2; mt++)
                    #pragma unroll
                    for (int nt = 0; nt < 8; nt++)
                        #pragma unroll
                        for (int i = 0; i < 4; i++) acc[mt][nt][i] = 0.f;

                #pragma unroll 2
                for (int ks = 0; ks < 8; ks++) {
                    uint32_t ah[2][4], al[2][4];
                    const uint32_t aoff = abase + ((uint32_t)((ks * 2 + asel) ^ laneX) << 4);
                    ldsm_x4(ah[0], aoff);
                    ldsm_x4(ah[1], aoff + 16 * 256);
                    ldsm_x4(al[0], aoff + SM_ALO);
                    ldsm_x4(al[1], aoff + SM_ALO + 16 * 256);
                    const uint32_t boff = ((uint32_t)((ks * 2 + bsel) ^ laneX) << 4);
                    #pragma unroll
                    for (int ntp = 0; ntp < 4; ntp++) {
                        uint32_t bh[4], bl[4];
                        const uint32_t ba = brow + (uint32_t)ntp * (16 * 256) + boff;
                        ldsm_x4(bh, ba + SM_WH);
                        ldsm_x4(bl, ba + SM_WL);
                        #pragma unroll
                        for (int mt = 0; mt < 2; mt++) {
                            MMA_BF16(acc[mt][2 * ntp],     ah[mt], bh[0], bh[1]);
                            MMA_BF16(acc[mt][2 * ntp + 1], ah[mt], bh[2], bh[3]);
                            MMA_BF16(acc[mt][2 * ntp],     ah[mt], bl[0], bl[1]);
                            MMA_BF16(acc[mt][2 * ntp + 1], ah[mt], bl[2], bl[3]);
                            MMA_BF16(acc[mt][2 * ntp],     al[mt], bh[0], bh[1]);
                            MMA_BF16(acc[mt][2 * ntp + 1], al[mt], bh[2], bh[3]);
                        }
                    }
                }
                // scores: fragment (ntl,tig) holds d = 4*tig+ntl -> float4 k loads
                #pragma unroll
                for (int hh = 0; hh < 2; hh++) {
                    const int h = nq * 2 + hh;
                    const float* kh = k + (((size_t)b * H_ + h) * N_) * D_;
                    const float4 q4 = ((const float4*)(q_cur + h * 16))[tig];
                    #pragma unroll
                    for (int mt = 0; mt < 2; mt++) {
                        #pragma unroll
                        for (int r = 0; r < 2; r++) {
                            const int mg = t * TM + mblk + mt * 16 + r * 8 + g;
                            const float4 kv = *(const float4*)(kh + (size_t)mg * 16 + 4 * tig);
                            float s;
                            s  = (q4.x + acc[mt][hh * 4 + 0][2 * r]) * (kv.x + acc[mt][hh * 4 + 0][2 * r + 1]);
                            s += (q4.y + acc[mt][hh * 4 + 1][2 * r]) * (kv.y + acc[mt][hh * 4 + 1][2 * r + 1]);
                            s += (q4.z + acc[mt][hh * 4 + 2][2 * r]) * (kv.z + acc[mt][hh * 4 + 2][2 * r + 1]);
                            s += (q4.w + acc[mt][hh * 4 + 3][2 * r]) * (kv.w + acc[mt][hh * 4 + 3][2 * r + 1]);
                            s += __shfl_xor_sync(0xffffffffu, s, 1);
                            s += __shfl_xor_sync(0xffffffffu, s, 2);
                            if (tig == 0)
                                s_cur[h * N_ + mg] = s * 0.25f;   // 1/sqrt(16)
                        }
                    }
                }
            } else if (wid < 12) {
                // ---------------- convert tile s+1, prefetch s+2 ----------------
                const int s1 = idx * 8 + t + 1;
                if (s1 < nwin) {
                    char* AH = smem + SM_A + (s1 & 1) * SM_ABUF + mrow * 256;
                    char* AL = AH + SM_ALO;
                    const int xr = mrow & 7;
                    #pragma unroll
                    for (int j = 0; j < 16; j++) {
                        const int e = e0c + j * 4;
                        float4 f = zreg[j];
                        uint32_t h01 = pack_bf2(f.x, f.y);
                        uint32_t h23 = pack_bf2(f.z, f.w);
                        uint32_t l01 = pack_bf2(f.x - bf_lo(h01), f.y - bf_hi(h01));
                        uint32_t l23 = pack_bf2(f.z - bf_lo(h23), f.w - bf_hi(h23));
                        int sw = (((e >> 3) ^ xr) << 4) + (e & 4) * 2;
                        *(uint2*)(AH + sw) = make_uint2(h01, h23);
                        *(uint2*)(AL + sw) = make_uint2(l01, l23);
                    }
                }
                if (s1 + 1 < nwin) {
                    const float4* zp = (const float4*)zptr(z, cta, stride, s1 + 1, mrow, e0c);
                    #pragma unroll
                    for (int j = 0; j < 16; j++) zreg[j] = zp[j];
                }
            } else {
                // ---------------- softmax of previous job (windows 0..3) ----------------
                if (pj >= 0 && t < 4) {
                    if (t == 0) {
                        #pragma unroll
                        for (int hh = 0; hh < 2; hh++) {
                            float* sr = s_prev + (w2 * 2 + hh) * N_;
                            float mx = -1e30f;
                            for (int m = lane; m < N_; m += 32) mx = fmaxf(mx, sr[m]);
                            #pragma unroll
                            for (int o = 16; o > 0; o >>= 1)
                                mx = fmaxf(mx, __shfl_xor_sync(0xffffffffu, mx, o));
                            float ps = 0.f;
                            for (int m = lane; m < N_; m += 32) {
                                float e = __expf(sr[m] - mx);
                                sr[m] = e;
                                ps += e;
                            }
                            #pragma unroll
                            for (int o = 16; o > 0; o >>= 1)
                                ps += __shfl_xor_sync(0xffffffffu, ps, o);
                            if (hh == 0) sm_sum0 = ps; else sm_sum1 = ps;
                        }
                    } else if (t <= 2) {
                        const int hh = lane >> 4, d = lane & 15;
                        const int h = w2 * 2 + hh;
                        const float* sr = s_prev + h * N_;
                        const float* vp = v + (((size_t)(pj >> 9) * H_ + h) * N_) * D_;
                        const int m0 = (t - 1) * (N_ / 2);
                        float oa = sm_oacc;
                        #pragma unroll 4
                        for (int m = m0; m < m0 + N_ / 2; m++)
                            oa += sr[m] * vp[(size_t)m * D_ + d];
                        sm_oacc = oa;
                    } else {
                        const int hh = lane >> 4, d = lane & 15;
                        const int h = w2 * 2 + hh;
                        const float sum = hh ? sm_sum1 : sm_sum0;
                        out[((size_t)(pj >> 9) * N_ + (pj & 511)) * HD + h * 16 + d] =
                            sm_oacc / sum;
                    }
                }
                // window 6: warp 12 loads q for next job into the other parity buffer
                if (t == 6 && w2 == 0) {
                    const int nj = job + stride;
                    if (nj < NJOBS_TOTAL) {
                        const int qb = nj >> 9, qn = nj & 511;
                        float4 qv = *(const float4*)(q +
                            (((size_t)qb * H_ + (lane >> 2)) * N_ + qn) * D_ + (lane & 3) * 4);
                        ((float4*)(smem + SM_Q))[(parity ^ 1) * 32 + lane] = qv;
                    }
                }
            }
            __syncthreads();
        }
    }

    // ======================= TAIL: softmax of the LAST job (all 16 warps) =======================
    {
        const int pj = cta + (njobs - 1) * stride;
        const int pb = pj >> 9, pn = pj & 511;
        float* s_base = (float*)(smem + SM_S) + ((njobs - 1) & 1) * (H_ * N_);
        const int h    = wid & 7;
        const int half = wid >> 3;
        float* srow = s_base + h * N_;

        float mx = -1e30f;
        for (int m = lane; m < N_; m += 32) mx = fmaxf(mx, srow[m]);
        #pragma unroll
        for (int o = 16; o > 0; o >>= 1) mx = fmaxf(mx, __shfl_xor_sync(0xffffffffu, mx, o));

        float psum = 0.f;
        const int mbeg = half * (N_ / 2);
        for (int m = mbeg + lane; m < mbeg + N_ / 2; m += 32) {
            float e = __expf(srow[m] - mx);
            srow[m] = e;
            psum += e;
        }
        #pragma unroll
        for (int o = 16; o > 0; o >>= 1) psum += __shfl_xor_sync(0xffffffffu, psum, o);
        if (lane == 0) red_sm[h * 2 + half] = psum;
        __syncthreads();
        const float sum = red_sm[h * 2] + red_sm[h * 2 + 1];

        const int d   = lane & 15;
        const int sub = lane >> 4;
        const float* vp = v + (((size_t)pb * H_ + h) * N_) * D_;
        float oacc = 0.f;
        const int m0 = mbeg + sub * (N_ / 4);
        #pragma unroll 4
        for (int m = m0; m < m0 + N_ / 4; m++)
            oacc += srow[m] * vp[(size_t)m * D_ + d];
        oacc += __shfl_xor_sync(0xffffffffu, oacc, 16);
        if (half == 1 && sub == 0) obuf[h * 16 + d] = oacc;
        __syncthreads();
        if (half == 0 && sub == 0)
            out[((size_t)pb * N_ + pn) * HD + h * 16 + d] = (oacc + obuf[h * 16 + d]) / sum;
    }
}

extern "C" void kernel_launch(void* const* d_in, const int* in_sizes, int n_in,
                              void* d_out, int out_size) {
    const float* q   = (const float*)d_in[0];
    const float* k   = (const float*)d_in[1];
    const float* v   = (const float*)d_in[2];
    const float* z   = (const float*)d_in[3];
    const float* Wz1 = (const float*)d_in[4];
    const float* Wz2 = (const float*)d_in[5];
    float* out = (float*)d_out;

    int sms = 0;
    cudaDeviceGetAttribute(&sms, cudaDevAttrMultiProcessorCount, 0);
    if (sms <= 0) sms = 148;
    int grid = sms < NJOBS_TOTAL ? sms : NJOBS_TOTAL;

    cudaFuncSetAttribute(mixed_attn_persist,
                         cudaFuncAttributeMaxDynamicSharedMemorySize, SM_TOTAL);
    mixed_attn_persist<<<grid, THREADS, SM_TOTAL>>>(q, k, v, z, Wz1, Wz2, out);
}

// round 11
// speedup vs baseline: 1.4637x; 1.4637x over previous
#include <cuda_runtime.h>
#include <cuda_fp16.h>
#include <cstdint>

// Problem constants
#define B_ 2
#define H_ 8
#define N_ 512
#define D_ 16
#define E_ 128
#define HD 128
#define TM 64               // m-rows per tile
#define NTILES 8
#define THREADS 512

// smem layout (bytes). A/W rows are 128 fp16 = 256 B.
#define SM_Q     0                      // 512 B   q row, head-major
#define SM_S     512                    // 16384 B scores [H][N]
#define SM_RED   16896                  // 64 B    softmax partials [H][2]
#define SM_OBUF  16960                  // 512 B   output partials [H][16]
#define SM_A     17920                  // 2 x 32768 B : {z_hi[64][128], z_lo[64][128]} x 2 bufs
#define SM_ABUF  32768
#define SM_ALO   16384                  // lo offset within a buffer
#define SM_WH    (SM_A + 2 * SM_ABUF)   // 65536 B W fp16 [256n][128k] (d-permuted, interleaved Wz1/Wz2)
#define SM_TOTAL (SM_WH + 65536)        // 148992 B

__device__ __forceinline__ uint32_t smem_u32(const void* p) {
    uint32_t r;
    asm("{ .reg .u64 t; cvta.to.shared.u64 t, %1; cvt.u32.u64 %0, t; }" : "=r"(r) : "l"(p));
    return r;
}
__device__ __forceinline__ void ldsm_x4(uint32_t (&r)[4], uint32_t addr) {
    asm volatile("ldmatrix.sync.aligned.m8n8.x4.shared.b16 {%0,%1,%2,%3}, [%4];"
                 : "=r"(r[0]), "=r"(r[1]), "=r"(r[2]), "=r"(r[3]) : "r"(addr));
}
#define MMA_F16(d, a, b0v, b1v) \
    asm volatile("mma.sync.aligned.m16n8k16.row.col.f32.f16.f16.f32 " \
        "{%0,%1,%2,%3}, {%4,%5,%6,%7}, {%8,%9}, {%0,%1,%2,%3};" \
        : "+f"((d)[0]), "+f"((d)[1]), "+f"((d)[2]), "+f"((d)[3]) \
        : "r"((a)[0]), "r"((a)[1]), "r"((a)[2]), "r"((a)[3]), "r"(b0v), "r"(b1v))

// pack (a,b) -> fp16x2 word, a in low half
__device__ __forceinline__ uint32_t pack_hf2(__half a, __half b) {
    __half2 p = __halves2half2(a, b);
    return *reinterpret_cast<uint32_t*>(&p);
}

__global__ void __launch_bounds__(THREADS, 1)
mixed_attn_ws(const float* __restrict__ q, const float* __restrict__ k,
              const float* __restrict__ v, const float* __restrict__ z,
              const float* __restrict__ Wz1, const float* __restrict__ Wz2,
              float* __restrict__ out)
{
    extern __shared__ char smem[];
    const uint32_t smem_base = smem_u32(smem);
    float* q_sm   = (float*)(smem + SM_Q);
    float* s_sm   = (float*)(smem + SM_S);
    float* red_sm = (float*)(smem + SM_RED);
    float* obuf   = (float*)(smem + SM_OBUF);

    const int tid  = threadIdx.x;
    const int wid  = tid >> 5;
    const int lane = tid & 31;
    const int g    = lane >> 2;
    const int tig  = lane & 3;
    const int n = blockIdx.x, b = blockIdx.y;

    // =========================== PROLOGUE ===========================
    if (wid < 8) {
        // ---- consumers: q + W -> fp16 (single term).
        // d-PERMUTED column placement: smem n-row nn encodes
        //   h = nn>>5, ntl = (nn>>3)&3, tg = (nn>>1)&3, src = nn&1
        //   source col c = h*16 + 4*tg + ntl of (src? Wz2 : Wz1)
        // => fragment position (ntl, tig) sees d = 4*tig + ntl (contiguous per thread).
        if (tid < HD) {
            int h = tid >> 4, d = tid & 15;
            q_sm[tid] = q[(((size_t)b * H_ + h) * N_ + n) * D_ + d];
        }
        const int nn = tid;               // 0..255, one W row per thread
        const float* Wsrc = (nn & 1) ? Wz2 : Wz1;
        const int c = (nn >> 5) * 16 + ((nn >> 1) & 3) * 4 + ((nn >> 3) & 3);
        char* WH = smem + SM_WH + nn * 256;
        const int xr = (nn & 7);
        #pragma unroll 4
        for (int e = 0; e < E_; e += 2) {
            float w0 = Wsrc[e * HD + c];
            float w1 = Wsrc[(e + 1) * HD + c];
            uint32_t hi = pack_hf2(__float2half_rn(w0), __float2half_rn(w1));
            int sw = ((((e >> 3) ^ xr) << 4)) + (e & 7) * 2;
            *(uint32_t*)(WH + sw) = hi;
        }
    }

    // producer thread mapping (rows of the 64-row tile)
    const int mrow = ((wid - 8) << 3) + (lane >> 2);   // 0..63 for producers
    const int e0   = (lane & 3) * 32;
    const float* zrow = z + (((size_t)b * N_ + n) * N_ + mrow) * E_ + e0;
    float4 zreg[8];

    if (wid >= 8) {
        // ---- producers: z tile 0 -> fp16 2-term convert -> A buf 0 ; prefetch tile 1
        #pragma unroll
        for (int j = 0; j < 8; j++) zreg[j] = ((const float4*)zrow)[j];
        {
            char* AH = smem + SM_A + mrow * 256;
            char* AL = smem + SM_A + SM_ALO + mrow * 256;
            const int xr = mrow & 7;
            #pragma unroll
            for (int j = 0; j < 8; j++) {
                const int e = e0 + j * 4;
                float4 f = zreg[j];
                __half hx = __float2half_rn(f.x), hy = __float2half_rn(f.y);
                __half hz = __float2half_rn(f.z), hw = __float2half_rn(f.w);
                uint32_t h01 = pack_hf2(hx, hy);
                uint32_t h23 = pack_hf2(hz, hw);
                uint32_t l01 = pack_hf2(__float2half_rn(f.x - __half2float(hx)),
                                        __float2half_rn(f.y - __half2float(hy)));
                uint32_t l23 = pack_hf2(__float2half_rn(f.z - __half2float(hz)),
                                        __float2half_rn(f.w - __half2float(hw)));
                int sw = (((e >> 3) ^ xr) << 4) + (e & 4) * 2;
                *(uint2*)(AH + sw) = make_uint2(h01, h23);
                *(uint2*)(AL + sw) = make_uint2(l01, l23);
            }
        }
        #pragma unroll
        for (int j = 0; j < 8; j++) zreg[j] = ((const float4*)(zrow + (size_t)TM * E_))[j];
    }
    __syncthreads();   // W, q, A0 ready

    // consumer warp tiling: 8 warps = 2 m-blocks (32 rows) x 4 n-blocks (64 cols = 2 heads)
    const int mblk  = (wid & 1) * 32;
    const int nq    = wid >> 1;            // 0..3 for consumers
    const int nbase = nq * 64;

    const int laneX = lane & 7;
    const uint32_t arow_off = (uint32_t)(mblk + ((lane >> 3) & 1) * 8 + laneX) * 256;
    const int asel = lane >> 4;
    const uint32_t brow = smem_base + (uint32_t)(nbase + ((lane >> 4) & 1) * 8 + laneX) * 256;
    const int bsel = (lane >> 3) & 1;

    // ========================== MAIN WINDOWS ==========================
    for (int t = 0; t < NTILES; t++) {
        if (wid < 8) {
            // ---------------- consumers: MMA tile t from A[t&1] ----------------
            const uint32_t abase = smem_base + SM_A + (uint32_t)(t & 1) * SM_ABUF + arow_off;

            float acc[2][8][4];
            #pragma unroll
            for (int mt = 0; mt < 2; mt++)
                #pragma unroll
                for (int nt = 0; nt < 8; nt++)
                    #pragma unroll
                    for (int i = 0; i < 4; i++) acc[mt][nt][i] = 0.f;

            #pragma unroll 2
            for (int ks = 0; ks < 8; ks++) {
                uint32_t ah[2][4], al[2][4];
                const uint32_t aoff = abase + ((uint32_t)((ks * 2 + asel) ^ laneX) << 4);
                ldsm_x4(ah[0], aoff);
                ldsm_x4(ah[1], aoff + 16 * 256);
                ldsm_x4(al[0], aoff + SM_ALO);
                ldsm_x4(al[1], aoff + SM_ALO + 16 * 256);
                const uint32_t boff = ((uint32_t)((ks * 2 + bsel) ^ laneX) << 4);
                #pragma unroll
                for (int ntp = 0; ntp < 4; ntp++) {
                    uint32_t bh[4];
                    const uint32_t ba = brow + (uint32_t)ntp * (16 * 256) + boff;
                    ldsm_x4(bh, ba + SM_WH);
                    #pragma unroll
                    for (int mt = 0; mt < 2; mt++) {
                        MMA_F16(acc[mt][2 * ntp],     ah[mt], bh[0], bh[1]);
                        MMA_F16(acc[mt][2 * ntp + 1], ah[mt], bh[2], bh[3]);
                        MMA_F16(acc[mt][2 * ntp],     al[mt], bh[0], bh[1]);
                        MMA_F16(acc[mt][2 * ntp + 1], al[mt], bh[2], bh[3]);
                    }
                }
            }

            // ---- scores from fragments.
            // d-permuted W: fragment (ntl, tig) holds d = 4*tig + ntl,
            // so each thread's 4 d-values per row are CONTIGUOUS -> one float4 k load.
            #pragma unroll
            for (int hh = 0; hh < 2; hh++) {
                const int h = nq * 2 + hh;
                const float* kh = k + (((size_t)b * H_ + h) * N_) * D_;
                const float4 q4 = ((const float4*)(q_sm + h * 16))[tig];
                #pragma unroll
                for (int mt = 0; mt < 2; mt++) {
                    #pragma unroll
                    for (int r = 0; r < 2; r++) {
                        const int mg = t * TM + mblk + mt * 16 + r * 8 + g;
                        const float4 kv = *(const float4*)(kh + (size_t)mg * 16 + 4 * tig);
                        float s;
                        s  = (q4.x + acc[mt][hh * 4 + 0][2 * r]) * (kv.x + acc[mt][hh * 4 + 0][2 * r + 1]);
                        s += (q4.y + acc[mt][hh * 4 + 1][2 * r]) * (kv.y + acc[mt][hh * 4 + 1][2 * r + 1]);
                        s += (q4.z + acc[mt][hh * 4 + 2][2 * r]) * (kv.z + acc[mt][hh * 4 + 2][2 * r + 1]);
                        s += (q4.w + acc[mt][hh * 4 + 3][2 * r]) * (kv.w + acc[mt][hh * 4 + 3][2 * r + 1]);
                        s += __shfl_xor_sync(0xffffffffu, s, 1);
                        s += __shfl_xor_sync(0xffffffffu, s, 2);
                        if (tig == 0)
                            s_sm[h * N_ + mg] = s * 0.25f;   // 1/sqrt(D), D=16
                    }
                }
            }
        } else {
            // ---------------- producers: convert tile t+1 into A[(t+1)&1] ----------------
            if (t + 1 < NTILES) {
                char* AH = smem + SM_A + ((t + 1) & 1) * SM_ABUF + mrow * 256;
                char* AL = AH + SM_ALO;
                const int xr = mrow & 7;
                #pragma unroll
                for (int j = 0; j < 8; j++) {
                    const int e = e0 + j * 4;
                    float4 f = zreg[j];
                    __half hx = __float2half_rn(f.x), hy = __float2half_rn(f.y);
                    __half hz = __float2half_rn(f.z), hw = __float2half_rn(f.w);
                    uint32_t h01 = pack_hf2(hx, hy);
                    uint32_t h23 = pack_hf2(hz, hw);
                    uint32_t l01 = pack_hf2(__float2half_rn(f.x - __half2float(hx)),
                                            __float2half_rn(f.y - __half2float(hy)));
                    uint32_t l23 = pack_hf2(__float2half_rn(f.z - __half2float(hz)),
                                            __float2half_rn(f.w - __half2float(hw)));
                    int sw = (((e >> 3) ^ xr) << 4) + (e & 4) * 2;
                    *(uint2*)(AH + sw) = make_uint2(h01, h23);
                    *(uint2*)(AL + sw) = make_uint2(l01, l23);
                }
            }
            if (t + 2 < NTILES) {
                const float4* zp = (const float4*)(zrow + (size_t)(t + 2) * TM * E_);
                #pragma unroll
                for (int j = 0; j < 8; j++) zreg[j] = zp[j];
            }
        }
        __syncthreads();
    }

    // ---- softmax + output: 2 warps per head (wid&7 = head, wid>>3 = m-half)
    {
        const int h    = wid & 7;
        const int half = wid >> 3;
        float* srow = s_sm + h * N_;

        float mx = -1e30f;
        for (int m = lane; m < N_; m += 32) mx = fmaxf(mx, srow[m]);
        #pragma unroll
        for (int o = 16; o > 0; o >>= 1) mx = fmaxf(mx, __shfl_xor_sync(0xffffffffu, mx, o));

        float psum = 0.f;
        const int mbeg = half * (N_ / 2);
        for (int m = mbeg + lane; m < mbeg + N_ / 2; m += 32) {
            float e = __expf(srow[m] - mx);
            srow[m] = e;
            psum += e;
        }
        #pragma unroll
        for (int o = 16; o > 0; o >>= 1) psum += __shfl_xor_sync(0xffffffffu, psum, o);
        if (lane == 0) red_sm[h * 2 + half] = psum;
        __syncthreads();
        const float sum = red_sm[h * 2] + red_sm[h * 2 + 1];

        const int d   = lane & 15;
        const int sub = lane >> 4;
        const float* vp = v + (((size_t)b * H_ + h) * N_) * D_;
        float oacc = 0.f;
        const int m0 = mbeg + sub * (N_ / 4);
        #pragma unroll 4
        for (int m = m0; m < m0 + N_ / 4; m++)
            oacc += srow[m] * vp[(size_t)m * D_ + d];
        oacc += __shfl_xor_sync(0xffffffffu, oacc, 16);
        if (half == 1 && sub == 0) obuf[h * 16 + d] = oacc;
        __syncthreads();
        if (half == 0 && sub == 0)
            out[((size_t)b * N_ + n) * HD + h * 16 + d] = (oacc + obuf[h * 16 + d]) / sum;
    }
}

extern "C" void kernel_launch(void* const* d_in, const int* in_sizes, int n_in,
                              void* d_out, int out_size) {
    const float* q   = (const float*)d_in[0];
    const float* k   = (const float*)d_in[1];
    const float* v   = (const float*)d_in[2];
    const float* z   = (const float*)d_in[3];
    const float* Wz1 = (const float*)d_in[4];
    const float* Wz2 = (const float*)d_in[5];
    float* out = (float*)d_out;

    cudaFuncSetAttribute(mixed_attn_ws,
                         cudaFuncAttributeMaxDynamicSharedMemorySize, SM_TOTAL);
    dim3 grid(N_, B_);
    mixed_attn_ws<<<grid, THREADS, SM_TOTAL>>>(q, k, v, z, Wz1, Wz2, out);
}

// round 12
// speedup vs baseline: 1.7303x; 1.1821x over previous
#include <cuda_runtime.h>
#include <cuda_fp16.h>
#include <cstdint>

// Problem constants
#define B_ 2
#define H_ 8
#define N_ 512
#define D_ 16
#define E_ 128
#define HD 128
#define TM 64               // m-rows per tile
#define NTILES 8
#define THREADS 512

// smem layout (bytes). A/W rows are 128 fp16 = 256 B.
#define SM_Q     0                      // 512 B   q row, head-major
#define SM_S     512                    // 16384 B scores [H][N]
#define SM_RED   16896                  // 64 B    softmax partials [H][2]
#define SM_OBUF  16960                  // 512 B   output partials [H][16]
#define SM_A     17920                  // 2 x 16384 B : z fp16 [64m][128k] x 2 bufs
#define SM_ABUF  16384
#define SM_WH    (SM_A + 2 * SM_ABUF)   // 65536 B W fp16 [256n][128k] (d-permuted, interleaved Wz1/Wz2)
#define SM_TOTAL (SM_WH + 65536)        // 116224 B

__device__ __forceinline__ uint32_t smem_u32(const void* p) {
    uint32_t r;
    asm("{ .reg .u64 t; cvta.to.shared.u64 t, %1; cvt.u32.u64 %0, t; }" : "=r"(r) : "l"(p));
    return r;
}
__device__ __forceinline__ void ldsm_x4(uint32_t (&r)[4], uint32_t addr) {
    asm volatile("ldmatrix.sync.aligned.m8n8.x4.shared.b16 {%0,%1,%2,%3}, [%4];"
                 : "=r"(r[0]), "=r"(r[1]), "=r"(r[2]), "=r"(r[3]) : "r"(addr));
}
#define MMA_F16(d, a, b0v, b1v) \
    asm volatile("mma.sync.aligned.m16n8k16.row.col.f32.f16.f16.f32 " \
        "{%0,%1,%2,%3}, {%4,%5,%6,%7}, {%8,%9}, {%0,%1,%2,%3};" \
        : "+f"((d)[0]), "+f"((d)[1]), "+f"((d)[2]), "+f"((d)[3]) \
        : "r"((a)[0]), "r"((a)[1]), "r"((a)[2]), "r"((a)[3]), "r"(b0v), "r"(b1v))

// pack (a,b) -> fp16x2 word, a in low half
__device__ __forceinline__ uint32_t pack_hf2(__half a, __half b) {
    __half2 p = __halves2half2(a, b);
    return *reinterpret_cast<uint32_t*>(&p);
}

__global__ void __launch_bounds__(THREADS, 1)
mixed_attn_ws(const float* __restrict__ q, const float* __restrict__ k,
              const float* __restrict__ v, const float* __restrict__ z,
              const float* __restrict__ Wz1, const float* __restrict__ Wz2,
              float* __restrict__ out)
{
    extern __shared__ char smem[];
    const uint32_t smem_base = smem_u32(smem);
    float* q_sm   = (float*)(smem + SM_Q);
    float* s_sm   = (float*)(smem + SM_S);
    float* red_sm = (float*)(smem + SM_RED);
    float* obuf   = (float*)(smem + SM_OBUF);

    const int tid  = threadIdx.x;
    const int wid  = tid >> 5;
    const int lane = tid & 31;
    const int g    = lane >> 2;
    const int tig  = lane & 3;
    const int n = blockIdx.x, b = blockIdx.y;

    // =========================== PROLOGUE ===========================
    if (wid < 8) {
        // ---- consumers: q + W -> fp16 (single term).
        // d-PERMUTED column placement: smem n-row nn encodes
        //   h = nn>>5, ntl = (nn>>3)&3, tg = (nn>>1)&3, src = nn&1
        //   source col c = h*16 + 4*tg + ntl of (src? Wz2 : Wz1)
        // => fragment position (ntl, tig) sees d = 4*tig + ntl (contiguous per thread).
        if (tid < HD) {
            int h = tid >> 4, d = tid & 15;
            q_sm[tid] = q[(((size_t)b * H_ + h) * N_ + n) * D_ + d];
        }
        const int nn = tid;               // 0..255, one W row per thread
        const float* Wsrc = (nn & 1) ? Wz2 : Wz1;
        const int c = (nn >> 5) * 16 + ((nn >> 1) & 3) * 4 + ((nn >> 3) & 3);
        char* WH = smem + SM_WH + nn * 256;
        const int xr = (nn & 7);
        #pragma unroll 4
        for (int e = 0; e < E_; e += 2) {
            float w0 = Wsrc[e * HD + c];
            float w1 = Wsrc[(e + 1) * HD + c];
            uint32_t hi = pack_hf2(__float2half_rn(w0), __float2half_rn(w1));
            int sw = ((((e >> 3) ^ xr) << 4)) + (e & 7) * 2;
            *(uint32_t*)(WH + sw) = hi;
        }
    }

    // producer thread mapping (rows of the 64-row tile)
    const int mrow = ((wid - 8) << 3) + (lane >> 2);   // 0..63 for producers
    const int e0   = (lane & 3) * 32;
    const float* zrow = z + (((size_t)b * N_ + n) * N_ + mrow) * E_ + e0;
    float4 zreg[8];

    if (wid >= 8) {
        // ---- producers: z tile 0 -> fp16 convert -> A buf 0 ; prefetch tile 1
        #pragma unroll
        for (int j = 0; j < 8; j++) zreg[j] = ((const float4*)zrow)[j];
        {
            char* AH = smem + SM_A + mrow * 256;
            const int xr = mrow & 7;
            #pragma unroll
            for (int j = 0; j < 8; j++) {
                const int e = e0 + j * 4;
                float4 f = zreg[j];
                uint32_t h01 = pack_hf2(__float2half_rn(f.x), __float2half_rn(f.y));
                uint32_t h23 = pack_hf2(__float2half_rn(f.z), __float2half_rn(f.w));
                int sw = (((e >> 3) ^ xr) << 4) + (e & 4) * 2;
                *(uint2*)(AH + sw) = make_uint2(h01, h23);
            }
        }
        #pragma unroll
        for (int j = 0; j < 8; j++) zreg[j] = ((const float4*)(zrow + (size_t)TM * E_))[j];
    }
    __syncthreads();   // W, q, A0 ready

    // consumer warp tiling: 8 warps = 2 m-blocks (32 rows) x 4 n-blocks (64 cols = 2 heads)
    const int mblk  = (wid & 1) * 32;
    const int nq    = wid >> 1;            // 0..3 for consumers
    const int nbase = nq * 64;

    const int laneX = lane & 7;
    const uint32_t arow_off = (uint32_t)(mblk + ((lane >> 3) & 1) * 8 + laneX) * 256;
    const int asel = lane >> 4;
    const uint32_t brow = smem_base + (uint32_t)(nbase + ((lane >> 4) & 1) * 8 + laneX) * 256;
    const int bsel = (lane >> 3) & 1;

    // ========================== MAIN WINDOWS ==========================
    for (int t = 0; t < NTILES; t++) {
        if (wid < 8) {
            // ---------------- consumers: MMA tile t from A[t&1] ----------------
            const uint32_t abase = smem_base + SM_A + (uint32_t)(t & 1) * SM_ABUF + arow_off;

            float acc[2][8][4];
            #pragma unroll
            for (int mt = 0; mt < 2; mt++)
                #pragma unroll
                for (int nt = 0; nt < 8; nt++)
                    #pragma unroll
                    for (int i = 0; i < 4; i++) acc[mt][nt][i] = 0.f;

            #pragma unroll 2
            for (int ks = 0; ks < 8; ks++) {
                uint32_t ah[2][4];
                const uint32_t aoff = abase + ((uint32_t)((ks * 2 + asel) ^ laneX) << 4);
                ldsm_x4(ah[0], aoff);
                ldsm_x4(ah[1], aoff + 16 * 256);
                const uint32_t boff = ((uint32_t)((ks * 2 + bsel) ^ laneX) << 4);
                #pragma unroll
                for (int ntp = 0; ntp < 4; ntp++) {
                    uint32_t bh[4];
                    const uint32_t ba = brow + (uint32_t)ntp * (16 * 256) + boff;
                    ldsm_x4(bh, ba + SM_WH);
                    #pragma unroll
                    for (int mt = 0; mt < 2; mt++) {
                        MMA_F16(acc[mt][2 * ntp],     ah[mt], bh[0], bh[1]);
                        MMA_F16(acc[mt][2 * ntp + 1], ah[mt], bh[2], bh[3]);
                    }
                }
            }

            // ---- scores from fragments.
            // d-permuted W: fragment (ntl, tig) holds d = 4*tig + ntl,
            // so each thread's 4 d-values per row are CONTIGUOUS -> one float4 k load.
            #pragma unroll
            for (int hh = 0; hh < 2; hh++) {
                const int h = nq * 2 + hh;
                const float* kh = k + (((size_t)b * H_ + h) * N_) * D_;
                const float4 q4 = ((const float4*)(q_sm + h * 16))[tig];
                #pragma unroll
                for (int mt = 0; mt < 2; mt++) {
                    #pragma unroll
                    for (int r = 0; r < 2; r++) {
                        const int mg = t * TM + mblk + mt * 16 + r * 8 + g;
                        const float4 kv = *(const float4*)(kh + (size_t)mg * 16 + 4 * tig);
                        float s;
                        s  = (q4.x + acc[mt][hh * 4 + 0][2 * r]) * (kv.x + acc[mt][hh * 4 + 0][2 * r + 1]);
                        s += (q4.y + acc[mt][hh * 4 + 1][2 * r]) * (kv.y + acc[mt][hh * 4 + 1][2 * r + 1]);
                        s += (q4.z + acc[mt][hh * 4 + 2][2 * r]) * (kv.z + acc[mt][hh * 4 + 2][2 * r + 1]);
                        s += (q4.w + acc[mt][hh * 4 + 3][2 * r]) * (kv.w + acc[mt][hh * 4 + 3][2 * r + 1]);
                        s += __shfl_xor_sync(0xffffffffu, s, 1);
                        s += __shfl_xor_sync(0xffffffffu, s, 2);
                        if (tig == 0)
                            s_sm[h * N_ + mg] = s * 0.25f;   // 1/sqrt(D), D=16
                    }
                }
            }
        } else {
            // ---------------- producers: convert tile t+1 into A[(t+1)&1] ----------------
            if (t + 1 < NTILES) {
                char* AH = smem + SM_A + ((t + 1) & 1) * SM_ABUF + mrow * 256;
                const int xr = mrow & 7;
                #pragma unroll
                for (int j = 0; j < 8; j++) {
                    const int e = e0 + j * 4;
                    float4 f = zreg[j];
                    uint32_t h01 = pack_hf2(__float2half_rn(f.x), __float2half_rn(f.y));
                    uint32_t h23 = pack_hf2(__float2half_rn(f.z), __float2half_rn(f.w));
                    int sw = (((e >> 3) ^ xr) << 4) + (e & 4) * 2;
                    *(uint2*)(AH + sw) = make_uint2(h01, h23);
                }
            }
            if (t + 2 < NTILES) {
                const float4* zp = (const float4*)(zrow + (size_t)(t + 2) * TM * E_);
                #pragma unroll
                for (int j = 0; j < 8; j++) zreg[j] = zp[j];
            }
        }
        __syncthreads();
    }

    // ---- softmax + output: 2 warps per head (wid&7 = head, wid>>3 = m-half)
    {
        const int h    = wid & 7;
        const int half = wid >> 3;
        float* srow = s_sm + h * N_;

        float mx = -1e30f;
        for (int m = lane; m < N_; m += 32) mx = fmaxf(mx, srow[m]);
        #pragma unroll
        for (int o = 16; o > 0; o >>= 1) mx = fmaxf(mx, __shfl_xor_sync(0xffffffffu, mx, o));

        float psum = 0.f;
        const int mbeg = half * (N_ / 2);
        for (int m = mbeg + lane; m < mbeg + N_ / 2; m += 32) {
            float e = __expf(srow[m] - mx);
            srow[m] = e;
            psum += e;
        }
        #pragma unroll
        for (int o = 16; o > 0; o >>= 1) psum += __shfl_xor_sync(0xffffffffu, psum, o);
        if (lane == 0) red_sm[h * 2 + half] = psum;
        __syncthreads();
        const float sum = red_sm[h * 2] + red_sm[h * 2 + 1];

        const int d   = lane & 15;
        const int sub = lane >> 4;
        const float* vp = v + (((size_t)b * H_ + h) * N_) * D_;
        float oacc = 0.f;
        const int m0 = mbeg + sub * (N_ / 4);
        #pragma unroll 4
        for (int m = m0; m < m0 + N_ / 4; m++)
            oacc += srow[m] * vp[(size_t)m * D_ + d];
        oacc += __shfl_xor_sync(0xffffffffu, oacc, 16);
        if (half == 1 && sub == 0) obuf[h * 16 + d] = oacc;
        __syncthreads();
        if (half == 0 && sub == 0)
            out[((size_t)b * N_ + n) * HD + h * 16 + d] = (oacc + obuf[h * 16 + d]) / sum;
    }
}

extern "C" void kernel_launch(void* const* d_in, const int* in_sizes, int n_in,
                              void* d_out, int out_size) {
    const float* q   = (const float*)d_in[0];
    const float* k   = (const float*)d_in[1];
    const float* v   = (const float*)d_in[2];
    const float* z   = (const float*)d_in[3];
    const float* Wz1 = (const float*)d_in[4];
    const float* Wz2 = (const float*)d_in[5];
    float* out = (float*)d_out;

    cudaFuncSetAttribute(mixed_attn_ws,
                         cudaFuncAttributeMaxDynamicSharedMemorySize, SM_TOTAL);
    dim3 grid(N_, B_);
    mixed_attn_ws<<<grid, THREADS, SM_TOTAL>>>(q, k, v, z, Wz1, Wz2, out);
}

// round 13
// speedup vs baseline: 1.8966x; 1.0961x over previous
#include <cuda_runtime.h>
#include <cuda_fp16.h>
#include <cstdint>

// Problem constants
#define B_ 2
#define H_ 8
#define N_ 512
#define D_ 16
#define E_ 128
#define HD 128
#define THREADS 512

// smem layout (bytes). A/W rows are 128 fp16 = 256 B.
#define SM_Q     0                      // 512 B    q row, head-major
#define SM_S     512                    // 16384 B  scores [H][N]
#define SM_RED   16896                  // 64 B     softmax partials [H][2]
#define SM_OBUF  16960                  // 512 B    output partials [H][16]
#define SM_A     17920                  // 131072 B z fp16 [512m][128k] (FULL, resident)
#define SM_W     (SM_A + 131072)        // 65536 B  W fp16 [256n][128k] (d-permuted, interleaved)
#define SM_TOTAL (SM_W + 65536)         // 214528 B

__device__ __forceinline__ uint32_t smem_u32(const void* p) {
    uint32_t r;
    asm("{ .reg .u64 t; cvta.to.shared.u64 t, %1; cvt.u32.u64 %0, t; }" : "=r"(r) : "l"(p));
    return r;
}
__device__ __forceinline__ void ldsm_x4(uint32_t (&r)[4], uint32_t addr) {
    asm volatile("ldmatrix.sync.aligned.m8n8.x4.shared.b16 {%0,%1,%2,%3}, [%4];"
                 : "=r"(r[0]), "=r"(r[1]), "=r"(r[2]), "=r"(r[3]) : "r"(addr));
}
#define MMA_F16(d, a, b0v, b1v) \
    asm volatile("mma.sync.aligned.m16n8k16.row.col.f32.f16.f16.f32 " \
        "{%0,%1,%2,%3}, {%4,%5,%6,%7}, {%8,%9}, {%0,%1,%2,%3};" \
        : "+f"((d)[0]), "+f"((d)[1]), "+f"((d)[2]), "+f"((d)[3]) \
        : "r"((a)[0]), "r"((a)[1]), "r"((a)[2]), "r"((a)[3]), "r"(b0v), "r"(b1v))

__device__ __forceinline__ uint32_t pack_hf2(__half a, __half b) {
    __half2 p = __halves2half2(a, b);
    return *reinterpret_cast<uint32_t*>(&p);
}

__global__ void __launch_bounds__(THREADS, 1)
mixed_attn_free(const float* __restrict__ q, const float* __restrict__ k,
                const float* __restrict__ v, const float* __restrict__ z,
                const float* __restrict__ Wz1, const float* __restrict__ Wz2,
                float* __restrict__ out)
{
    extern __shared__ char smem[];
    const uint32_t smem_base = smem_u32(smem);
    float* q_sm   = (float*)(smem + SM_Q);
    float* s_sm   = (float*)(smem + SM_S);
    float* red_sm = (float*)(smem + SM_RED);
    float* obuf   = (float*)(smem + SM_OBUF);

    const int tid  = threadIdx.x;
    const int wid  = tid >> 5;
    const int lane = tid & 31;
    const int g    = lane >> 2;
    const int tig  = lane & 3;
    const int n = blockIdx.x, b = blockIdx.y;

    // =========================== PHASE 1: cooperative convert ===========================
    // z: one full m-row per thread (128 floats, contiguous 512 B) -> fp16 A row
    {
        const float4* zr = (const float4*)(z + (((size_t)b * N_ + n) * N_ + tid) * E_);
        char* AH = smem + SM_A + tid * 256;
        const int xr = tid & 7;
        #pragma unroll 1
        for (int j0 = 0; j0 < 32; j0 += 8) {
            float4 f[8];
            #pragma unroll
            for (int j = 0; j < 8; j++) f[j] = zr[j0 + j];
            #pragma unroll
            for (int j = 0; j < 8; j++) {
                const int e = (j0 + j) * 4;
                uint32_t h01 = pack_hf2(__float2half_rn(f[j].x), __float2half_rn(f[j].y));
                uint32_t h23 = pack_hf2(__float2half_rn(f[j].z), __float2half_rn(f[j].w));
                int sw = (((e >> 3) ^ xr) << 4) + (e & 4) * 2;
                *(uint2*)(AH + sw) = make_uint2(h01, h23);
            }
        }
    }
    // W -> fp16, d-PERMUTED columns (fragment (ntl,tig) sees d = 4*tig+ntl):
    //   nn: h = nn>>5, ntl = (nn>>3)&3, tg = (nn>>1)&3, src = nn&1
    //   source col c = h*16 + 4*tg + ntl of (src? Wz2 : Wz1). 2 threads per row.
    {
        const int nn = tid >> 1;
        const int eh = (tid & 1) * 64;
        const float* Wsrc = (nn & 1) ? Wz2 : Wz1;
        const int c = (nn >> 5) * 16 + ((nn >> 1) & 3) * 4 + ((nn >> 3) & 3);
        char* WH = smem + SM_W + nn * 256;
        const int xr = (nn & 7);
        #pragma unroll 4
        for (int e = eh; e < eh + 64; e += 2) {
            float w0 = Wsrc[e * HD + c];
            float w1 = Wsrc[(e + 1) * HD + c];
            uint32_t hi = pack_hf2(__float2half_rn(w0), __float2half_rn(w1));
            int sw = ((((e >> 3) ^ xr) << 4)) + (e & 7) * 2;
            *(uint32_t*)(WH + sw) = hi;
        }
    }
    // q row, head-major
    if (tid < HD) {
        int h = tid >> 4, d = tid & 15;
        q_sm[tid] = q[(((size_t)b * H_ + h) * N_ + n) * D_ + d];
    }
    __syncthreads();   // A, W, q all resident

    // =========================== PHASE 2: barrier-free MMA + scores ===========================
    // 16 warps = 4 m-groups x 4 n-groups; each warp: 4 chunks of 32m x 64n (2 heads), K=128.
    {
        const int mgrp  = wid & 3;
        const int ngrp  = wid >> 2;
        const int nbase = ngrp * 64;
        const int laneX = lane & 7;
        const uint32_t arow = smem_base + SM_A +
            (uint32_t)(mgrp * 32 + ((lane >> 3) & 1) * 8 + laneX) * 256;
        const int asel = lane >> 4;
        const uint32_t brow = smem_base + SM_W +
            (uint32_t)(nbase + ((lane >> 4) & 1) * 8 + laneX) * 256;
        const int bsel = (lane >> 3) & 1;

        const int h0 = ngrp * 2;
        const float* kh0 = k + (((size_t)b * H_ + h0) * N_) * D_;
        const float* kh1 = k + (((size_t)b * H_ + h0 + 1) * N_) * D_;
        const float4 q40 = ((const float4*)(q_sm + h0 * 16))[tig];
        const float4 q41 = ((const float4*)(q_sm + (h0 + 1) * 16))[tig];

        #pragma unroll 1
        for (int chunk = 0; chunk < 4; chunk++) {
            const uint32_t abase = arow + (uint32_t)chunk * (128 * 256);

            float acc[2][8][4];
            #pragma unroll
            for (int mt = 0; mt < 2; mt++)
                #pragma unroll
                for (int nt = 0; nt < 8; nt++)
                    #pragma unroll
                    for (int i = 0; i < 4; i++) acc[mt][nt][i] = 0.f;

            #pragma unroll 2
            for (int ks = 0; ks < 8; ks++) {
                uint32_t ah[2][4];
                const uint32_t aoff = abase + ((uint32_t)((ks * 2 + asel) ^ laneX) << 4);
                ldsm_x4(ah[0], aoff);
                ldsm_x4(ah[1], aoff + 16 * 256);
                const uint32_t boff = ((uint32_t)((ks * 2 + bsel) ^ laneX) << 4);
                #pragma unroll
                for (int ntp = 0; ntp < 4; ntp++) {
                    uint32_t bh[4];
                    ldsm_x4(bh, brow + (uint32_t)ntp * (16 * 256) + boff);
                    #pragma unroll
                    for (int mt = 0; mt < 2; mt++) {
                        MMA_F16(acc[mt][2 * ntp],     ah[mt], bh[0], bh[1]);
                        MMA_F16(acc[mt][2 * ntp + 1], ah[mt], bh[2], bh[3]);
                    }
                }
            }

            // scores: fragment (ntl,tig) holds d = 4*tig+ntl -> one float4 k load per row
            #pragma unroll
            for (int hh = 0; hh < 2; hh++) {
                const int h = h0 + hh;
                const float* kh = hh ? kh1 : kh0;
                const float4 q4 = hh ? q41 : q40;
                #pragma unroll
                for (int mt = 0; mt < 2; mt++) {
                    #pragma unroll
                    for (int r = 0; r < 2; r++) {
                        const int mg = chunk * 128 + mgrp * 32 + mt * 16 + r * 8 + g;
                        const float4 kv = *(const float4*)(kh + (size_t)mg * 16 + 4 * tig);
                        float s;
                        s  = (q4.x + acc[mt][hh * 4 + 0][2 * r]) * (kv.x + acc[mt][hh * 4 + 0][2 * r + 1]);
                        s += (q4.y + acc[mt][hh * 4 + 1][2 * r]) * (kv.y + acc[mt][hh * 4 + 1][2 * r + 1]);
                        s += (q4.z + acc[mt][hh * 4 + 2][2 * r]) * (kv.z + acc[mt][hh * 4 + 2][2 * r + 1]);
                        s += (q4.w + acc[mt][hh * 4 + 3][2 * r]) * (kv.w + acc[mt][hh * 4 + 3][2 * r + 1]);
                        s += __shfl_xor_sync(0xffffffffu, s, 1);
                        s += __shfl_xor_sync(0xffffffffu, s, 2);
                        if (tig == 0)
                            s_sm[h * N_ + mg] = s * 0.25f;   // 1/sqrt(D), D=16
                    }
                }
            }
        }
    }
    __syncthreads();   // all scores written

    // =========================== PHASE 3: softmax + output ===========================
    {
        const int h    = wid & 7;
        const int half = wid >> 3;
        float* srow = s_sm + h * N_;

        float mx = -1e30f;
        for (int m = lane; m < N_; m += 32) mx = fmaxf(mx, srow[m]);
        #pragma unroll
        for (int o = 16; o > 0; o >>= 1) mx = fmaxf(mx, __shfl_xor_sync(0xffffffffu, mx, o));

        float psum = 0.f;
        const int mbeg = half * (N_ / 2);
        for (int m = mbeg + lane; m < mbeg + N_ / 2; m += 32) {
            float e = __expf(srow[m] - mx);
            srow[m] = e;
            psum += e;
        }
        #pragma unroll
        for (int o = 16; o > 0; o >>= 1) psum += __shfl_xor_sync(0xffffffffu, psum, o);
        if (lane == 0) red_sm[h * 2 + half] = psum;
        __syncthreads();
        const float sum = red_sm[h * 2] + red_sm[h * 2 + 1];

        const int d   = lane & 15;
        const int sub = lane >> 4;
        const float* vp = v + (((size_t)b * H_ + h) * N_) * D_;
        float oacc = 0.f;
        const int m0 = mbeg + sub * (N_ / 4);
        #pragma unroll 4
        for (int m = m0; m < m0 + N_ / 4; m++)
            oacc += srow[m] * vp[(size_t)m * D_ + d];
        oacc += __shfl_xor_sync(0xffffffffu, oacc, 16);
        if (half == 1 && sub == 0) obuf[h * 16 + d] = oacc;
        __syncthreads();
        if (half == 0 && sub == 0)
            out[((size_t)b * N_ + n) * HD + h * 16 + d] = (oacc + obuf[h * 16 + d]) / sum;
    }
}

extern "C" void kernel_launch(void* const* d_in, const int* in_sizes, int n_in,
                              void* d_out, int out_size) {
    const float* q   = (const float*)d_in[0];
    const float* k   = (const float*)d_in[1];
    const float* v   = (const float*)d_in[2];
    const float* z   = (const float*)d_in[3];
    const float* Wz1 = (const float*)d_in[4];
    const float* Wz2 = (const float*)d_in[5];
    float* out = (float*)d_out;

    cudaFuncSetAttribute(mixed_attn_free,
                         cudaFuncAttributeMaxDynamicSharedMemorySize, SM_TOTAL);
    dim3 grid(N_, B_);
    mixed_attn_free<<<grid, THREADS, SM_TOTAL>>>(q, k, v, z, Wz1, Wz2, out);
}